// round 15
// baseline (speedup 1.0000x reference)
#include <cuda_runtime.h>
#include <cuda_pipeline.h>

#define VOCABN 5000
#define NB 16
#define NS 128
#define NT 512
#define NL 257            // 2*NS + 1
#define RSF 264           // emit row stride in floats (1056 B, 16B-aligned)
#define ALPHA_W 0.2f
#define SMOOTH 0.1f
#define PRODB (NB * 2 * 32)   // 1024 producer blocks (one per chunk per dir per batch)
#define ATTB  (NB * NS)       // 2048 att row blocks

__device__ float g_emit[NB * 2 * 256 * RSF];  // [b][dir][k 0..255][state 0..255], 8.65 MB
__device__ int   g_flag[NB * 2 * 32];          // one per 8-row chunk

__device__ __forceinline__ float a2_into(const int* tb, int x) {
    if ((x & 1) && x >= 3 && x < NL) {
        int e  = __ldg(tb + (x >> 1));
        int ep = __ldg(tb + (x >> 1) - 1);
        return (e != 0 && e != ep) ? 1.0f : 0.0f;
    }
    return 0.0f;
}

__device__ __forceinline__ float warp_max_pos(float m) {
    // all operands non-negative -> fp32 ordering == u32 ordering
    return __uint_as_float(__reduce_max_sync(0xffffffffu, __float_as_uint(m)));
}

__device__ __forceinline__ void poll_flag(const int* f) {
    if ((threadIdx.x & 31) == 0)
        while (*(volatile const int*)f == 0) __nanosleep(40);
    __syncwarp();
}

// stage one 8-row chunk (rows k0..k0+7) into the 16-row smem ring
__device__ __forceinline__ void stage_chunk(float* ring, const float* g, int k0, int lane) {
    #pragma unroll
    for (int kk = 0; kk < 8; ++kk) {
        const int k = k0 + kk;
        const float* src = g + (size_t)k * RSF + 8 * lane;
        float* dst = &ring[(k & 15) * RSF + 8 * lane];
        __pipeline_memcpy_async(dst,     src,     16);
        __pipeline_memcpy_async(dst + 4, src + 4, 16);
    }
}

__global__ __launch_bounds__(288) void fused_kernel(
    const float* __restrict__ att,   // (16,128,5000)
    const float* __restrict__ ctc,   // (16,512,5000) log-probs per reference
    const int*   __restrict__ tgt,   // (16,128)
    float* __restrict__ out)
{
    __shared__ __align__(16) float ringF[16 * RSF];
    __shared__ __align__(16) float ringB[16 * RSF];
    __shared__ float aS[264], bS[264];
    __shared__ float sFS, sBS;
    __shared__ float red[9];

    const int tid = threadIdx.x;
    const int blk = blockIdx.x;

    if (blk < NB) {
        // ================= consumer block: batch `blk` =================
        const int lane = tid & 31;
        const float* cb = ctc + (size_t)blk * NT * VOCABN;
        const int*   tb = tgt + blk * NS;

        if (tid < 32) {
            // ---------- forward scan: t = 1..255 ----------
            const float* gF = g_emit + (size_t)(blk * 2 + 0) * 256 * RSF;
            const int*   fF = g_flag + (blk * 2 + 0) * 32;

            float a2[8];
            #pragma unroll
            for (int j = 0; j < 8; ++j) a2[j] = a2_into(tb, 8 * lane + j);

            float v[8], v8 = 0.0f;
            #pragma unroll
            for (int j = 0; j < 8; ++j) v[j] = 0.0f;
            if (lane == 0) {
                v[0] = __expf(__ldg(cb + 0));
                v[1] = __expf(__ldg(cb + __ldg(tb + 0)));
            }

            poll_flag(fF + 0);
            stage_chunk(ringF, gF, 0, lane);
            __pipeline_commit();                         // group: chunk 0

            float sF = 0.0f;
            for (int tt = 0; tt < 32; ++tt) {
                if (tt + 1 < 32) {                        // prefetch next chunk
                    poll_flag(fF + tt + 1);
                    stage_chunk(ringF, gF, (tt + 1) * 8, lane);
                }
                __pipeline_commit();
                __pipeline_wait_prior(1);                // chunk tt landed
                #pragma unroll
                for (int i = 0; i < 8; ++i) {
                    const int k = tt * 8 + i;            // t = k+1
                    if (k < 255) {
                        const float* rs = &ringF[(k & 15) * RSF + 8 * lane];
                        float4 EA = *(const float4*)rs;
                        float4 EB = *(const float4*)(rs + 4);
                        float E8 = __shfl_sync(0xffffffffu, EA.x, 0);  // blank
                        float x1 = __shfl_up_sync(0xffffffffu, v[7], 1);
                        float x2 = __shfl_up_sync(0xffffffffu, v[6], 1);
                        if (lane == 0) { x1 = 0.0f; x2 = 0.0f; }
                        float n0 = (v[0] + x1)   + a2[0] * x2;
                        float n1 = (v[1] + v[0]) + a2[1] * x1;
                        float n2 = (v[2] + v[1]) + a2[2] * v[0];
                        float n3 = (v[3] + v[2]) + a2[3] * v[1];
                        float n4 = (v[4] + v[3]) + a2[4] * v[2];
                        float n5 = (v[5] + v[4]) + a2[5] * v[3];
                        float n6 = (v[6] + v[5]) + a2[6] * v[4];
                        float n7 = (v[7] + v[6]) + a2[7] * v[5];
                        float n8 = v8 + v[7];
                        v[0] = n0 * EA.x; v[1] = n1 * EA.y;
                        v[2] = n2 * EA.z; v[3] = n3 * EA.w;
                        v[4] = n4 * EB.x; v[5] = n5 * EB.y;
                        v[6] = n6 * EB.z; v[7] = n7 * EB.w;
                        v8   = n8 * E8;
                    }
                }
                float m01 = fmaxf(v[0], v[1]), m23 = fmaxf(v[2], v[3]);
                float m45 = fmaxf(v[4], v[5]), m67 = fmaxf(v[6], v[7]);
                float m = fmaxf(fmaxf(m01, m23), fmaxf(fmaxf(m45, m67), v8));
                m = warp_max_pos(m);
                float r = __fdividef(1.0f, m);
                #pragma unroll
                for (int j = 0; j < 8; ++j) v[j] *= r;
                v8 *= r;
                sF += __logf(m);
            }
            #pragma unroll
            for (int j = 0; j < 8; ++j) aS[8 * lane + j] = v[j];
            if (lane == 31) aS[256] = v8;
            if (lane == 0) sFS = sF;
        } else if (tid < 64) {
            // ---------- backward scan: t = 510..256 (init at 511) ----------
            const float* gB = g_emit + (size_t)(blk * 2 + 1) * 256 * RSF;
            const int*   fB = g_flag + (blk * 2 + 1) * 32;

            float a2b[8];
            #pragma unroll
            for (int j = 0; j < 8; ++j) a2b[j] = a2_into(tb, 8 * lane + j + 2);

            float v[8], v8 = 0.0f;
            #pragma unroll
            for (int j = 0; j < 8; ++j) v[j] = 0.0f;
            if (lane == 31) {
                const float* r511 = cb + (size_t)511 * VOCABN;
                v[7] = __expf(__ldg(r511 + __ldg(tb + 127)));   // state 255
                v8   = __expf(__ldg(r511));                      // state 256 = blank
            }

            poll_flag(fB + 0);
            stage_chunk(ringB, gB, 0, lane);
            __pipeline_commit();

            float sB = 0.0f;
            for (int tt = 0; tt < 32; ++tt) {
                if (tt + 1 < 32) {
                    poll_flag(fB + tt + 1);
                    stage_chunk(ringB, gB, (tt + 1) * 8, lane);
                }
                __pipeline_commit();
                __pipeline_wait_prior(1);
                #pragma unroll
                for (int i = 0; i < 8; ++i) {
                    const int k = tt * 8 + i;            // t = 510-k
                    if (k < 255) {
                        const float* rs = &ringB[(k & 15) * RSF + 8 * lane];
                        float4 EA = *(const float4*)rs;
                        float4 EB = *(const float4*)(rs + 4);
                        float E8 = __shfl_sync(0xffffffffu, EA.x, 0);
                        float x1 = __shfl_down_sync(0xffffffffu, v[0], 1); // state 8l+8
                        float x2 = __shfl_down_sync(0xffffffffu, v[1], 1); // state 8l+9
                        if (lane == 31) { x1 = v8; x2 = 0.0f; }
                        float n0 = (v[0] + v[1]) + a2b[0] * v[2];
                        float n1 = (v[1] + v[2]) + a2b[1] * v[3];
                        float n2 = (v[2] + v[3]) + a2b[2] * v[4];
                        float n3 = (v[3] + v[4]) + a2b[3] * v[5];
                        float n4 = (v[4] + v[5]) + a2b[4] * v[6];
                        float n5 = (v[5] + v[6]) + a2b[5] * v[7];
                        float n6 = (v[6] + v[7]) + a2b[6] * x1;
                        float n7 = (v[7] + x1)   + a2b[7] * x2;
                        float n8 = v8;                            // state 256: self only
                        v[0] = n0 * EA.x; v[1] = n1 * EA.y;
                        v[2] = n2 * EA.z; v[3] = n3 * EA.w;
                        v[4] = n4 * EB.x; v[5] = n5 * EB.y;
                        v[6] = n6 * EB.z; v[7] = n7 * EB.w;
                        v8   = n8 * E8;
                    }
                }
                float m01 = fmaxf(v[0], v[1]), m23 = fmaxf(v[2], v[3]);
                float m45 = fmaxf(v[4], v[5]), m67 = fmaxf(v[6], v[7]);
                float m = fmaxf(fmaxf(m01, m23), fmaxf(fmaxf(m45, m67), v8));
                m = warp_max_pos(m);
                float r = __fdividef(1.0f, m);
                #pragma unroll
                for (int j = 0; j < 8; ++j) v[j] *= r;
                v8 *= r;
                sB += __logf(m);
            }
            #pragma unroll
            for (int j = 0; j < 8; ++j) bS[8 * lane + j] = v[j];
            if (lane == 31) { bS[256] = v8; bS[257] = 0.0f; bS[258] = 0.0f; }
            if (lane == 0) sBS = sB;
        }

        __syncthreads();       // warps >= 2 have exited; only scan warps arrive

        if (tid < 32) {
            float dot = 0.0f;
            #pragma unroll
            for (int j = 0; j < 8; ++j) {
                int s = 8 * lane + j;
                float C = bS[s] + bS[s + 1] + a2_into(tb, s + 2) * bS[s + 2];
                dot += aS[s] * C;
            }
            if (lane == 31) dot += aS[256] * bS[256];
            #pragma unroll
            for (int o = 16; o > 0; o >>= 1)
                dot += __shfl_xor_sync(0xffffffffu, dot, o);
            if (lane == 0) {
                float ll = __logf(dot) + sFS + sBS;
                float lb = -ll;
                if (!(lb < 1e20f)) lb = 0.0f;      // zero_infinity (inf/nan too)
                atomicAdd(out, ((1.0f - ALPHA_W) / (float)(NB * NS)) * lb);
            }
        }
    } else if (blk < NB + PRODB) {
        // ================= producer block: one 8-row chunk =================
        const int p    = blk - NB;             // chunk-major: early t first
        const int c    = p >> 5;               // 0..31
        const int pair = p & 31;
        const int b    = pair >> 1;
        const int dir  = pair & 1;             // 0 = fwd, 1 = bwd
        const float* cb = ctc + (size_t)b * NT * VOCABN;

        if (tid < 256) {
            int ext = 0;
            if (tid & 1) ext = __ldg(tgt + b * NS + (tid >> 1));
            const float* col = cb + ext;
            float v[8];
            #pragma unroll
            for (int i = 0; i < 8; ++i) {
                const int k = c * 8 + i;
                const int t = dir ? (510 - k) : (1 + k);
                v[i] = __expf(__ldg(col + (size_t)t * VOCABN));
            }
            float* dst = g_emit + ((size_t)(b * 2 + dir) * 256 + c * 8) * RSF + tid;
            #pragma unroll
            for (int i = 0; i < 8; ++i) dst[i * RSF] = v[i];
        }
        __threadfence();
        __syncthreads();
        if (tid == 0) atomicExch(&g_flag[(b * 2 + dir) * 32 + c], 1);
    } else {
        // ================= label-smoothing row =================
        const int r = blk - NB - PRODB;         // 0..2047
        const float* row = att + (size_t)r * VOCABN;
        const int tv = __ldg(tgt + r);

        float s = 0.0f;
        const float4* row4 = (const float4*)row;   // 5000 % 4 == 0
        for (int i = tid; i < VOCABN / 4; i += 288) {
            float4 v = __ldg(&row4[i]);
            s += (v.x + v.y) + (v.z + v.w);
        }
        #pragma unroll
        for (int o = 16; o > 0; o >>= 1)
            s += __shfl_down_sync(0xffffffffu, s, o);
        const int wid = tid >> 5, lane = tid & 31;
        if (lane == 0) red[wid] = s;
        __syncthreads();
        if (tid == 0) {
            float total = 0.0f;
            #pragma unroll
            for (int w = 0; w < 9; ++w) total += red[w];
            float tl = __ldg(row + tv);
            const float conf = 1.0f - SMOOTH;
            const float off  = SMOOTH / (float)(VOCABN - 1);
            float per_row = -(off * total + (conf - off) * tl);
            atomicAdd(out, (ALPHA_W / 2048.0f) * per_row);
        }
    }
}

extern "C" void kernel_launch(void* const* d_in, const int* in_sizes, int n_in,
                              void* d_out, int out_size) {
    const float* att = (const float*)d_in[0];
    const float* ctc = (const float*)d_in[1];
    const int*   tgt = (const int*)d_in[2];
    float* out = (float*)d_out;

    void* flag_ptr = nullptr;
    cudaGetSymbolAddress(&flag_ptr, g_flag);

    cudaMemsetAsync(out, 0, sizeof(float));
    cudaMemsetAsync(flag_ptr, 0, sizeof(int) * NB * 2 * 32);
    fused_kernel<<<NB + PRODB + ATTB, 288>>>(att, ctc, tgt, out);
}

// round 16
// speedup vs baseline: 3.3183x; 3.3183x over previous
#include <cuda_runtime.h>
#include <cuda_pipeline.h>

#define VOCABN 5000
#define NB 16
#define NS 128
#define NT 512
#define NL 257            // 2*NS + 1
#define RSF 132           // emit row stride: 128 odd states + blank@[128] + pad (528B)
#define ALPHA_W 0.2f
#define SMOOTH 0.1f
#define DPTH 8            // cp.async ring depth (proven r8 setting)
#define GB 512            // gather blocks: 32 per batch, 16 t-rows each
#define TM 255            // meet point

__device__ float g_emit[NB * NT * RSF];   // 4.3 MB: [b][t][ o0..o127, blank, pad ]

// ===== kernel 1: parallel gather + exp (odd states + blank only) =====
__global__ __launch_bounds__(288) void gather_kernel(
    const float* __restrict__ ctc, const int* __restrict__ tgt,
    float* __restrict__ out)
{
    const int tid = threadIdx.x;
    const int b  = blockIdx.x >> 5;              // 512 blocks / 16 batches
    const int t0 = (blockIdx.x & 31) << 4;       // 16 t-rows per block
    const int g  = (tid >= 144);                 // two 8-row groups
    const int s  = tid - 144 * g;                // 0..143; active if s < 129
    const int tb = t0 + 8 * g;

    if (blockIdx.x == 0 && tid == 287) *out = 0.0f;   // scan kernel runs after

    if (s < 129) {
        // s < 128: odd state 2s+1 -> column tgt[s]; s == 128: blank column 0
        int ext = (s < 128) ? __ldg(tgt + b * NS + s) : 0;
        const float* col = ctc + (size_t)b * NT * VOCABN + ext;
        float v[8];
        #pragma unroll
        for (int i = 0; i < 8; ++i)
            v[i] = __expf(__ldg(col + (size_t)(tb + i) * VOCABN));
        float* dst = g_emit + ((size_t)b * NT + tb) * RSF + s;
        #pragma unroll
        for (int i = 0; i < 8; ++i) dst[i * RSF] = v[i];
    }
}

__device__ __forceinline__ float a2_into(const int* tb, int x) {
    if ((x & 1) && x >= 3 && x < NL) {
        int e  = __ldg(tb + (x >> 1));
        int ep = __ldg(tb + (x >> 1) - 1);
        return (e != 0 && e != ep) ? 1.0f : 0.0f;
    }
    return 0.0f;
}

__device__ __forceinline__ float warp_max_pos(float m) {
    // all operands non-negative -> fp32 ordering == u32 ordering
    return __uint_as_float(__reduce_max_sync(0xffffffffu, __float_as_uint(m)));
}

// ===== kernel 2: fwd+bwd meet-in-the-middle (blocks 0..15) + att loss =====
__global__ __launch_bounds__(288) void scan_att_kernel(
    const float* __restrict__ att, const int* __restrict__ tgt,
    float* __restrict__ out)
{
    __shared__ __align__(16) float ringF[DPTH * RSF];
    __shared__ __align__(16) float ringB[DPTH * RSF];
    __shared__ float aS[264], bS[264];
    __shared__ float sFS, sBS;
    __shared__ float red[9];

    const int tid = threadIdx.x;
    const int blk = blockIdx.x;

    if (blk < NB) {
        const int lane = tid & 31;
        const float* eb = g_emit + (size_t)blk * NT * RSF;
        const int*   tb = tgt + blk * NS;

        if (tid < 32) {
            // ---------------- forward warp: t = 1..255 ----------------
            float a2[8];
            #pragma unroll
            for (int j = 0; j < 8; ++j) a2[j] = a2_into(tb, 8 * lane + j);

            float v[8], v8 = 0.0f;
            #pragma unroll
            for (int j = 0; j < 8; ++j) v[j] = 0.0f;
            if (lane == 0) {
                // init directly from emit row t=0: blank@128, odd0@0
                v[0] = __ldg(eb + 128);
                v[1] = __ldg(eb + 0);
            }

            #pragma unroll
            for (int d = 0; d < DPTH; ++d) {
                const float* src = eb + (size_t)(1 + d) * RSF;
                __pipeline_memcpy_async(&ringF[d * RSF + 4 * lane], src + 4 * lane, 16);
                if (lane == 0)
                    __pipeline_memcpy_async(&ringF[d * RSF + 128], src + 128, 4);
                __pipeline_commit();
            }

            float sF = 0.0f;
            for (int tt = 0; tt < 32; ++tt) {
                #pragma unroll
                for (int i = 0; i < 8; ++i) {
                    const int t = 1 + tt * 8 + i;
                    if (t <= TM) {
                        __pipeline_wait_prior(DPTH - 1);   // row t landed
                        const float* rs = &ringF[i * RSF];
                        float4 O  = *(const float4*)(rs + 4 * lane);
                        float  bE = rs[128];               // broadcast
                        const int tp = t + DPTH;
                        if (tp <= TM) {
                            const float* src = eb + (size_t)tp * RSF;
                            __pipeline_memcpy_async(&ringF[i * RSF + 4 * lane], src + 4 * lane, 16);
                            if (lane == 0)
                                __pipeline_memcpy_async(&ringF[i * RSF + 128], src + 128, 4);
                        }
                        __pipeline_commit();               // one group per step
                        float x1 = __shfl_up_sync(0xffffffffu, v[7], 1);
                        float x2 = __shfl_up_sync(0xffffffffu, v[6], 1);
                        if (lane == 0) { x1 = 0.0f; x2 = 0.0f; }
                        float n0 = (v[0] + x1)   + a2[0] * x2;
                        float n1 = (v[1] + v[0]) + a2[1] * x1;
                        float n2 = (v[2] + v[1]) + a2[2] * v[0];
                        float n3 = (v[3] + v[2]) + a2[3] * v[1];
                        float n4 = (v[4] + v[3]) + a2[4] * v[2];
                        float n5 = (v[5] + v[4]) + a2[5] * v[3];
                        float n6 = (v[6] + v[5]) + a2[6] * v[4];
                        float n7 = (v[7] + v[6]) + a2[7] * v[5];
                        float n8 = v8 + v[7];
                        v[0] = n0 * bE;  v[1] = n1 * O.x;
                        v[2] = n2 * bE;  v[3] = n3 * O.y;
                        v[4] = n4 * bE;  v[5] = n5 * O.z;
                        v[6] = n6 * bE;  v[7] = n7 * O.w;
                        v8   = n8 * bE;
                    }
                }
                float m01 = fmaxf(v[0], v[1]), m23 = fmaxf(v[2], v[3]);
                float m45 = fmaxf(v[4], v[5]), m67 = fmaxf(v[6], v[7]);
                float m = fmaxf(fmaxf(m01, m23), fmaxf(fmaxf(m45, m67), v8));
                m = warp_max_pos(m);
                float r = __fdividef(1.0f, m);
                #pragma unroll
                for (int j = 0; j < 8; ++j) v[j] *= r;
                v8 *= r;
                sF += __logf(m);
            }
            #pragma unroll
            for (int j = 0; j < 8; ++j) aS[8 * lane + j] = v[j];
            if (lane == 31) aS[256] = v8;
            if (lane == 0) sFS = sF;
        } else if (tid < 64) {
            // ---------------- backward warp: t = 510..256 (init at 511) ----------------
            float a2b[8];
            #pragma unroll
            for (int j = 0; j < 8; ++j) a2b[j] = a2_into(tb, 8 * lane + j + 2);

            float v[8], v8 = 0.0f;
            #pragma unroll
            for (int j = 0; j < 8; ++j) v[j] = 0.0f;
            if (lane == 31) {
                const float* e511 = eb + (size_t)511 * RSF;
                v[7] = __ldg(e511 + 127);        // odd state 255 = o[127]
                v8   = __ldg(e511 + 128);        // state 256 = blank
            }

            #pragma unroll
            for (int d = 0; d < DPTH; ++d) {
                const float* src = eb + (size_t)(510 - d) * RSF;
                __pipeline_memcpy_async(&ringB[d * RSF + 4 * lane], src + 4 * lane, 16);
                if (lane == 0)
                    __pipeline_memcpy_async(&ringB[d * RSF + 128], src + 128, 4);
                __pipeline_commit();
            }

            float sB = 0.0f;
            for (int tt = 0; tt < 32; ++tt) {
                #pragma unroll
                for (int i = 0; i < 8; ++i) {
                    const int t = 510 - (tt * 8 + i);
                    if (t >= TM + 1) {
                        __pipeline_wait_prior(DPTH - 1);
                        const float* rs = &ringB[i * RSF];
                        float4 O  = *(const float4*)(rs + 4 * lane);
                        float  bE = rs[128];
                        const int tp = t - DPTH;
                        if (tp >= TM + 1) {
                            const float* src = eb + (size_t)tp * RSF;
                            __pipeline_memcpy_async(&ringB[i * RSF + 4 * lane], src + 4 * lane, 16);
                            if (lane == 0)
                                __pipeline_memcpy_async(&ringB[i * RSF + 128], src + 128, 4);
                        }
                        __pipeline_commit();
                        float x1 = __shfl_down_sync(0xffffffffu, v[0], 1); // state 8l+8
                        float x2 = __shfl_down_sync(0xffffffffu, v[1], 1); // state 8l+9
                        if (lane == 31) { x1 = v8; x2 = 0.0f; }
                        float n0 = (v[0] + v[1]) + a2b[0] * v[2];
                        float n1 = (v[1] + v[2]) + a2b[1] * v[3];
                        float n2 = (v[2] + v[3]) + a2b[2] * v[4];
                        float n3 = (v[3] + v[4]) + a2b[3] * v[5];
                        float n4 = (v[4] + v[5]) + a2b[4] * v[6];
                        float n5 = (v[5] + v[6]) + a2b[5] * v[7];
                        float n6 = (v[6] + v[7]) + a2b[6] * x1;
                        float n7 = (v[7] + x1)   + a2b[7] * x2;
                        float n8 = v8;                        // state 256: self only
                        v[0] = n0 * bE;  v[1] = n1 * O.x;
                        v[2] = n2 * bE;  v[3] = n3 * O.y;
                        v[4] = n4 * bE;  v[5] = n5 * O.z;
                        v[6] = n6 * bE;  v[7] = n7 * O.w;
                        v8   = n8 * bE;
                    }
                }
                float m01 = fmaxf(v[0], v[1]), m23 = fmaxf(v[2], v[3]);
                float m45 = fmaxf(v[4], v[5]), m67 = fmaxf(v[6], v[7]);
                float m = fmaxf(fmaxf(m01, m23), fmaxf(fmaxf(m45, m67), v8));
                m = warp_max_pos(m);
                float r = __fdividef(1.0f, m);
                #pragma unroll
                for (int j = 0; j < 8; ++j) v[j] *= r;
                v8 *= r;
                sB += __logf(m);
            }
            #pragma unroll
            for (int j = 0; j < 8; ++j) bS[8 * lane + j] = v[j];
            if (lane == 31) { bS[256] = v8; bS[257] = 0.0f; bS[258] = 0.0f; }
            if (lane == 0) sBS = sB;
        }

        __syncthreads();

        if (tid < 32) {
            const int lane = tid;
            float dot = 0.0f;
            #pragma unroll
            for (int j = 0; j < 8; ++j) {
                int s = 8 * lane + j;
                float C = bS[s] + bS[s + 1] + a2_into(tb, s + 2) * bS[s + 2];
                dot += aS[s] * C;
            }
            if (lane == 31) dot += aS[256] * bS[256];
            #pragma unroll
            for (int o = 16; o > 0; o >>= 1)
                dot += __shfl_xor_sync(0xffffffffu, dot, o);
            if (lane == 0) {
                float ll = __logf(dot) + sFS + sBS;
                float lb = -ll;
                if (!(lb < 1e20f)) lb = 0.0f;      // zero_infinity (inf/nan too)
                atomicAdd(out, ((1.0f - ALPHA_W) / (float)(NB * NS)) * lb);
            }
        }
    } else {
        // ================= label-smoothing row `blk - NB` =================
        const int r = blk - NB;
        const float* row = att + (size_t)r * VOCABN;
        const int tv = __ldg(tgt + r);

        float s = 0.0f;
        const float4* row4 = (const float4*)row;   // 5000 % 4 == 0
        for (int i = tid; i < VOCABN / 4; i += 288) {
            float4 v = __ldg(&row4[i]);
            s += (v.x + v.y) + (v.z + v.w);
        }
        #pragma unroll
        for (int o = 16; o > 0; o >>= 1)
            s += __shfl_down_sync(0xffffffffu, s, o);
        const int wid = tid >> 5, lane = tid & 31;
        if (lane == 0) red[wid] = s;
        __syncthreads();
        if (tid == 0) {
            float total = 0.0f;
            #pragma unroll
            for (int w = 0; w < 9; ++w) total += red[w];
            float tl = __ldg(row + tv);
            const float conf = 1.0f - SMOOTH;
            const float off  = SMOOTH / (float)(VOCABN - 1);
            float per_row = -(off * total + (conf - off) * tl);
            atomicAdd(out, (ALPHA_W / 2048.0f) * per_row);
        }
    }
}

extern "C" void kernel_launch(void* const* d_in, const int* in_sizes, int n_in,
                              void* d_out, int out_size) {
    const float* att = (const float*)d_in[0];
    const float* ctc = (const float*)d_in[1];
    const int*   tgt = (const int*)d_in[2];
    float* out = (float*)d_out;

    gather_kernel<<<GB, 288>>>(ctc, tgt, out);
    scan_att_kernel<<<NB + NB * NS, 288>>>(att, tgt, out);
}